// round 1
// baseline (speedup 1.0000x reference)
#include <cuda_runtime.h>
#include <math.h>

#define N 4096
#define NTHREADS 1024
#define INV_REG 1.0f   // regularization_strength = 1.0
#define W1C 1.0f
#define W2C 1.0f

// Block-wide sum reduction. scratch must hold >= 32 floats.
__device__ __forceinline__ float blockReduceSum(float v, float* scratch) {
#pragma unroll
    for (int o = 16; o; o >>= 1) v += __shfl_down_sync(0xffffffffu, v, o);
    int w = threadIdx.x >> 5, l = threadIdx.x & 31;
    __syncthreads();                 // protect scratch reuse across calls
    if (l == 0) scratch[w] = v;
    __syncthreads();
    if (w == 0) {
        float t = scratch[l];        // exactly 32 warps
#pragma unroll
        for (int o = 16; o; o >>= 1) t += __shfl_down_sync(0xffffffffu, t, o);
        if (l == 0) scratch[0] = t;
    }
    __syncthreads();
    return scratch[0];
}

// Dynamic SMEM layout:
//   float val[N]; float rankP[N]; float rankT[N]; float stS[N]; float red[32];
//   int idx[N]; int stStart[N+1]; int nb;
#define SMEM_BYTES ((4 * N + 32) * 4 + (2 * N + 2) * 4)

__global__ __launch_bounds__(NTHREADS, 1)
void SpearmanWithBCE_kernel(const float* __restrict__ yhat,
                            const float* __restrict__ ytar,
                            float* __restrict__ out) {
    extern __shared__ float smem[];
    float* val     = smem;
    float* rankP   = val + N;
    float* rankT   = rankP + N;
    float* stS     = rankT + N;      // PAV stack: block sum of s (small part)
    float* red     = stS + N;        // 32 floats reduction scratch
    int*   idx     = (int*)(red + 32);
    int*   stStart = idx + N;        // N+1 (sentinel)
    int*   nbPtr   = stStart + N + 1;

    const int tid = threadIdx.x;

    for (int row = 0; row < 2; ++row) {
        const float* src  = row ? ytar : yhat;
        float*       rank = row ? rankT : rankP;

        // ---- load theta = x / reg ----
        for (int i = tid; i < N; i += NTHREADS) {
            val[i] = src[i] * INV_REG;
            idx[i] = i;
        }
        __syncthreads();

        // ---- bitonic sort: descending by value, ascending index tiebreak
        //      (matches stable argsort(-theta)) ----
        for (int k = 2; k <= N; k <<= 1) {
            for (int j = k >> 1; j > 0; j >>= 1) {
                for (int i = tid; i < N; i += NTHREADS) {
                    int ixj = i ^ j;
                    if (ixj > i) {
                        float vi = val[i], vj = val[ixj];
                        int   ii = idx[i], ij = idx[ixj];
                        // "i before ixj" in our total order (desc value, asc idx)
                        bool iBefore = (vi > vj) || (vi == vj && ii < ij);
                        bool up = ((i & k) == 0);
                        if (up != iBefore) {
                            val[i] = vj; val[ixj] = vi;
                            idx[i] = ij; idx[ixj] = ii;
                        }
                    }
                }
                __syncthreads();
            }
        }

        // ---- PAV: nonincreasing isotonic fit of z_i = s_i - (N - i) ----
        // Track per block only sumS (small, accurate); the w-part is the exact
        // integer W(start,cnt) = cnt*N - sum(start..start+cnt-1), all < 2^24.
        // Stack top kept in registers; common path (monotone-increasing z)
        // never touches the SMEM stack.
        if (tid == 0) {
            float tS = val[0];               // top block: sum of s
            int   tC = 1, tSt = 0;           // count, start
            float tNum = tS - (float)N;      // sum of z over block = sumS - W
            int   nb = 0;                    // blocks below top (in SMEM)
            for (int i = 1; i < N; ++i) {
                float s  = val[i];
                float cS = s;
                int   cC = 1, cSt = i;
                float cNum = s - (float)(N - i);
                // violation (meanTop < meanCur) -> pool  [counts > 0]
                while (tNum * (float)cC < cNum * (float)tC) {
                    cS += tS; cC += tC; cSt = tSt;
                    int W = cC * N - (((2 * cSt + cC - 1) * cC) >> 1);
                    cNum = cS - (float)W;
                    if (nb == 0) { tC = 0; break; }   // stack empty
                    nb--;
                    int pSt = stStart[nb];
                    tS  = stS[nb];
                    tC  = cSt - pSt;
                    tSt = pSt;
                    int Wt = tC * N - (((2 * tSt + tC - 1) * tC) >> 1);
                    tNum = tS - (float)Wt;
                }
                if (tC > 0) { stS[nb] = tS; stStart[nb] = tSt; nb++; }
                tS = cS; tC = cC; tSt = cSt; tNum = cNum;
            }
            stS[nb] = tS; stStart[nb] = tSt; nb++;
            stStart[nb] = N;                 // sentinel
            *nbPtr = nb;
        }
        __syncthreads();

        int nb = *nbPtr;

        // ---- per-block dual mean: (sumS - W) / cnt  (overwrite stS) ----
        for (int b = tid; b < nb; b += NTHREADS) {
            int s0 = stStart[b], s1 = stStart[b + 1];
            int cnt = s1 - s0;
            int W = cnt * N - (((2 * s0 + cnt - 1) * cnt) >> 1);
            stS[b] = (stS[b] - (float)W) / (float)cnt;
        }
        __syncthreads();

        // ---- expand + scatter: rank'[perm[i]] = s_i - dual_b - (N+1)/2
        //      (global shift is Spearman-invariant; keeps ranks O(1)) ----
        for (int i = tid; i < N; i += NTHREADS) {
            int lo = 0, hi = nb - 1;
            while (lo < hi) {                       // largest b: start[b] <= i
                int mid = (lo + hi + 1) >> 1;
                if (stStart[mid] <= i) lo = mid; else hi = mid - 1;
            }
            rank[idx[i]] = val[i] - stS[lo] - 0.5f * (float)(N + 1);
        }
        __syncthreads();
    }

    // ---- reductions: means + BCE ----
    float sP = 0.f, sT = 0.f, sB = 0.f;
    for (int i = tid; i < N; i += NTHREADS) {
        sP += rankP[i];
        sT += rankT[i];
        float x  = yhat[i];
        float yy = ytar[i];
        // logaddexp(0,x) - x*y, stable
        sB += fmaxf(x, 0.f) + log1pf(expf(-fabsf(x))) - x * yy;
    }
    float meanP = blockReduceSum(sP, red) * (1.0f / (float)N);
    float meanT = blockReduceSum(sT, red) * (1.0f / (float)N);
    float bce   = blockReduceSum(sB, red) * (1.0f / (float)N);

    float ssP = 0.f, ssT = 0.f, cr = 0.f;
    for (int i = tid; i < N; i += NTHREADS) {
        float dp = rankP[i] - meanP;
        float dt = rankT[i] - meanT;
        ssP += dp * dp;
        ssT += dt * dt;
        cr  += dp * dt;
    }
    ssP = blockReduceSum(ssP, red);
    ssT = blockReduceSum(ssT, red);
    cr  = blockReduceSum(cr, red);

    if (tid == 0) {
        float spearman = cr / sqrtf(ssP * ssT);
        out[0] = W1C * (1.0f - spearman) + W2C * bce;
    }
}

extern "C" void kernel_launch(void* const* d_in, const int* in_sizes, int n_in,
                              void* d_out, int out_size) {
    const float* yhat = (const float*)d_in[0];
    const float* ytar = (const float*)d_in[1];
    float* out = (float*)d_out;
    cudaFuncSetAttribute(SpearmanWithBCE_kernel,
                         cudaFuncAttributeMaxDynamicSharedMemorySize, SMEM_BYTES);
    SpearmanWithBCE_kernel<<<1, NTHREADS, SMEM_BYTES>>>(yhat, ytar, out);
}

// round 2
// speedup vs baseline: 9.7628x; 9.7628x over previous
#include <cuda_runtime.h>
#include <math.h>

#define N 4096
#define NTHREADS 1024
#define NCHUNK 64
#define CHUNK 64
#define W1C 1.0f
#define W2C 1.0f

typedef unsigned long long u64;
typedef unsigned int u32;

__device__ float g_rank[2][N];   // staged ranks (static device alloc — allowed)

// ---- float <-> order-preserving uint ----
__device__ __forceinline__ u32 encodeVal(float v) {
    u32 b = __float_as_uint(v);
    return (b & 0x80000000u) ? ~b : (b | 0x80000000u);
}
__device__ __forceinline__ float decodeVal(u32 khi) {
    u32 u = ~khi;  // khi = ~encodeVal(v)
    return (u & 0x80000000u) ? __uint_as_float(u ^ 0x80000000u)
                             : __uint_as_float(~u);
}

// exact integer W(start,cnt) = cnt*N - sum(start..start+cnt-1), as float
__device__ __forceinline__ float Wf(int s, int c) {
    return (float)(c * N - (((2 * s + c - 1) * c) >> 1));
}

__device__ __forceinline__ void cswap(u64& a, u64& b, bool up) {
    if ((a > b) == up) { u64 t = a; a = b; b = t; }
}

// SMEM: keys u64[N]; bStart i[N]; bCnt i[N]; bSum f[N]; fStart i[N+1]; fS f[N]; cnt i[64]; nb
#define SMEM_BYTES (N*8 + N*4*5 + 4 + 64*4 + 8)

__global__ __launch_bounds__(NTHREADS, 1)
void sortRankKernel(const float* __restrict__ yhat,
                    const float* __restrict__ ytar) {
    extern __shared__ u64 smemBase[];
    u64*   keys   = smemBase;                    // N
    int*   bStart = (int*)(keys + N);            // N
    int*   bCnt   = bStart + N;                  // N
    float* bSum   = (float*)(bCnt + N);          // N
    int*   fStart = (int*)(bSum + N);            // N+1
    float* fS     = (float*)(fStart + N + 1);    // N
    int*   cntArr = (int*)(fS + N);              // NCHUNK
    int*   nbPtr  = cntArr + NCHUNK;

    const int tid = threadIdx.x;
    const int row = blockIdx.x;
    const float* src = row ? ytar : yhat;

    // ---- load 4 elems/thread, build keys, do bitonic k=2 and k=4 in regs ----
    {
        int base = tid * 4;
        float4 v = *(const float4*)(src + base);
        u64 e0 = ((u64)(~encodeVal(v.x)) << 32) | (u32)(base + 0);
        u64 e1 = ((u64)(~encodeVal(v.y)) << 32) | (u32)(base + 1);
        u64 e2 = ((u64)(~encodeVal(v.z)) << 32) | (u32)(base + 2);
        u64 e3 = ((u64)(~encodeVal(v.w)) << 32) | (u32)(base + 3);
        // k=2: pair(0,1) asc, pair(2,3) desc
        cswap(e0, e1, true);
        cswap(e2, e3, false);
        // k=4
        bool d4 = ((base & 4) == 0);
        cswap(e0, e2, d4); cswap(e1, e3, d4);
        cswap(e0, e1, d4); cswap(e2, e3, d4);
        keys[base] = e0; keys[base + 1] = e1; keys[base + 2] = e2; keys[base + 3] = e3;
    }
    __syncthreads();

    // ---- bitonic k=8..N: j>=4 in SMEM, j=2,1 in registers ----
    for (int k = 8; k <= N; k <<= 1) {
        for (int j = k >> 1; j >= 4; j >>= 1) {
#pragma unroll
            for (int t = 0; t < 4; ++t) {
                int i = tid + t * NTHREADS;
                int p = i ^ j;
                if (p > i) {
                    u64 a = keys[i], b = keys[p];
                    bool up = ((i & k) == 0);
                    if ((a > b) == up) { keys[i] = b; keys[p] = a; }
                }
            }
            __syncthreads();
        }
        {
            int base = tid * 4;
            u64 e0 = keys[base], e1 = keys[base + 1], e2 = keys[base + 2], e3 = keys[base + 3];
            bool up = ((base & k) == 0);
            cswap(e0, e2, up); cswap(e1, e3, up);   // j=2
            cswap(e0, e1, up); cswap(e2, e3, up);   // j=1
            keys[base] = e0; keys[base + 1] = e1; keys[base + 2] = e2; keys[base + 3] = e3;
        }
        __syncthreads();
    }
    // keys now ascending  <=>  values descending, stable (asc index on ties)

    // ---- Phase A: per-chunk PAV (nonincreasing fit of z_i = s_i - (N-i)) ----
    if (tid < NCHUNK) {
        const int base = tid * CHUNK;
        int myCnt = 0;
        float tS  = decodeVal((u32)(keys[base] >> 32));
        int   tC  = 1, tSt = base;
        float tNum = tS - (float)(N - base);
        for (int i = base + 1; i < base + CHUNK; ++i) {
            float s  = decodeVal((u32)(keys[i] >> 32));
            float cS = s;
            int   cC = 1, cSt = i;
            float cNum = s - (float)(N - i);
            while (tNum * (float)cC < cNum * (float)tC) {
                cS += tS; cC += tC; cSt = tSt;
                cNum = cS - Wf(cSt, cC);
                if (myCnt == 0) { tC = 0; break; }
                myCnt--;
                tSt = bStart[base + myCnt];
                tS  = bSum[base + myCnt];
                tC  = bCnt[base + myCnt];
                tNum = tS - Wf(tSt, tC);
            }
            if (tC > 0) {
                bStart[base + myCnt] = tSt; bSum[base + myCnt] = tS; bCnt[base + myCnt] = tC;
                myCnt++;
            }
            tS = cS; tC = cC; tSt = cSt; tNum = cNum;
        }
        bStart[base + myCnt] = tSt; bSum[base + myCnt] = tS; bCnt[base + myCnt] = tC;
        cntArr[tid] = myCnt + 1;
    }
    __syncthreads();

    // ---- Phase B: serial merge of chunk block lists (blocks as atoms) ----
    if (tid == 0) {
        int nb = 0;
        int   tSt = bStart[0], tC = bCnt[0];
        float tS  = bSum[0];
        float tNum = tS - Wf(tSt, tC);
        for (int c = 0; c < NCHUNK; ++c) {
            int m = cntArr[c];
            for (int b = (c == 0) ? 1 : 0; b < m; ++b) {
                int off = c * CHUNK + b;
                int   cSt = bStart[off], cC = bCnt[off];
                float cS  = bSum[off];
                float cNum = cS - Wf(cSt, cC);
                while (tNum * (float)cC < cNum * (float)tC) {
                    cS += tS; cC += tC; cSt = tSt;
                    cNum = cS - Wf(cSt, cC);
                    if (nb == 0) { tC = 0; break; }
                    nb--;
                    int pSt = fStart[nb];
                    tS  = fS[nb];
                    tC  = cSt - pSt;
                    tSt = pSt;
                    tNum = tS - Wf(tSt, tC);
                }
                if (tC > 0) { fStart[nb] = tSt; fS[nb] = tS; nb++; }
                tS = cS; tC = cC; tSt = cSt; tNum = cNum;
            }
        }
        fStart[nb] = tSt; fS[nb] = tS; nb++;
        fStart[nb] = N;              // sentinel
        *nbPtr = nb;
    }
    __syncthreads();

    const int nb = *nbPtr;

    // ---- per-block dual mean ----
    for (int b = tid; b < nb; b += NTHREADS) {
        int s0 = fStart[b], cc = fStart[b + 1] - s0;
        fS[b] = (fS[b] - Wf(s0, cc)) / (float)cc;
    }
    __syncthreads();

    // ---- expand + scatter (shift by (N+1)/2, Spearman-invariant) ----
    for (int i = tid; i < N; i += NTHREADS) {
        u64 kk = keys[i];
        float s = decodeVal((u32)(kk >> 32));
        int  id = (int)(kk & 0xFFFFFFFFu);
        int lo = 0, hi = nb - 1;
        while (lo < hi) {
            int mid = (lo + hi + 1) >> 1;
            if (fStart[mid] <= i) lo = mid; else hi = mid - 1;
        }
        g_rank[row][id] = s - fS[lo] - 2048.5f;
    }
}

// ---------------- reduction kernel ----------------
__device__ __forceinline__ float blockReduceSum(float v, float* scratch, int nwarps) {
#pragma unroll
    for (int o = 16; o; o >>= 1) v += __shfl_down_sync(0xffffffffu, v, o);
    int w = threadIdx.x >> 5, l = threadIdx.x & 31;
    __syncthreads();
    if (l == 0) scratch[w] = v;
    __syncthreads();
    if (w == 0) {
        float t = (l < nwarps) ? scratch[l] : 0.f;
#pragma unroll
        for (int o = 16; o; o >>= 1) t += __shfl_down_sync(0xffffffffu, t, o);
        if (l == 0) scratch[0] = t;
    }
    __syncthreads();
    return scratch[0];
}

#define RTHREADS 512

__global__ __launch_bounds__(RTHREADS, 1)
void reduceKernel(const float* __restrict__ yhat,
                  const float* __restrict__ ytar,
                  float* __restrict__ out) {
    __shared__ float red[32];
    const int tid = threadIdx.x;

    float sP = 0.f, sT = 0.f, sB = 0.f;
    for (int i = tid; i < N; i += RTHREADS) {
        sP += g_rank[0][i];
        sT += g_rank[1][i];
        float x  = yhat[i];
        float yy = ytar[i];
        sB += fmaxf(x, 0.f) + log1pf(expf(-fabsf(x))) - x * yy;
    }
    float meanP = blockReduceSum(sP, red, RTHREADS / 32) * (1.0f / (float)N);
    float meanT = blockReduceSum(sT, red, RTHREADS / 32) * (1.0f / (float)N);
    float bce   = blockReduceSum(sB, red, RTHREADS / 32) * (1.0f / (float)N);

    float ssP = 0.f, ssT = 0.f, cr = 0.f;
    for (int i = tid; i < N; i += RTHREADS) {
        float dp = g_rank[0][i] - meanP;
        float dt = g_rank[1][i] - meanT;
        ssP += dp * dp;
        ssT += dt * dt;
        cr  += dp * dt;
    }
    ssP = blockReduceSum(ssP, red, RTHREADS / 32);
    ssT = blockReduceSum(ssT, red, RTHREADS / 32);
    cr  = blockReduceSum(cr, red, RTHREADS / 32);

    if (tid == 0) {
        float spearman = cr / sqrtf(ssP * ssT);
        out[0] = W1C * (1.0f - spearman) + W2C * bce;
    }
}

extern "C" void kernel_launch(void* const* d_in, const int* in_sizes, int n_in,
                              void* d_out, int out_size) {
    const float* yhat = (const float*)d_in[0];
    const float* ytar = (const float*)d_in[1];
    float* out = (float*)d_out;
    cudaFuncSetAttribute(sortRankKernel,
                         cudaFuncAttributeMaxDynamicSharedMemorySize, SMEM_BYTES);
    sortRankKernel<<<2, NTHREADS, SMEM_BYTES>>>(yhat, ytar);
    reduceKernel<<<1, RTHREADS>>>(yhat, ytar, out);
}

// round 3
// speedup vs baseline: 11.1405x; 1.1411x over previous
#include <cuda_runtime.h>
#include <math.h>

#define N 4096
#define NTHREADS 1024
#define NCHUNK 64
#define CHUNK 64

typedef unsigned long long u64;
typedef unsigned int u32;

__device__ float g_rank[2][N];
__device__ float g_sum[2];
__device__ float g_sumsq[2];
__device__ float g_bce;
__device__ u32   g_arrive;      // zero-init; reset by finisher each launch

// ---- float <-> order-preserving uint ----
__device__ __forceinline__ u32 encodeVal(float v) {
    u32 b = __float_as_uint(v);
    return (b & 0x80000000u) ? ~b : (b | 0x80000000u);
}
__device__ __forceinline__ float decodeVal(u32 khi) {
    u32 u = ~khi;
    return (u & 0x80000000u) ? __uint_as_float(u ^ 0x80000000u)
                             : __uint_as_float(~u);
}

// exact integer W(start,cnt) = cnt*N - sum(start..start+cnt-1)
__device__ __forceinline__ float Wf(int s, int c) {
    return (float)(c * N - (((2 * s + c - 1) * c) >> 1));
}

__device__ __forceinline__ u64 u64min(u64 a, u64 b) { return a < b ? a : b; }
__device__ __forceinline__ u64 u64max(u64 a, u64 b) { return a > b ? a : b; }

__device__ __forceinline__ void casReg(u64& a, u64& b, bool up) {
    u64 mn = u64min(a, b), mx = u64max(a, b);
    a = up ? mn : mx;
    b = up ? mx : mn;
}
__device__ __forceinline__ u64 casShfl(u64 e, int j, bool up, int l) {
    u64 o = __shfl_xor_sync(0xffffffffu, e, j);
    bool low = ((l & j) == 0);
    return (low == up) ? u64min(e, o) : u64max(e, o);
}

// Fully sort this warp's 128 elements (ascending). lane l holds base+32m+l in e[m].
__device__ __forceinline__ void warpSort128(u64 e[4], int base, int l) {
#pragma unroll
    for (int kk = 1; kk <= 7; kk++) {
        const int k = 1 << kk;
#pragma unroll
        for (int jj = kk - 1; jj >= 0; jj--) {
            const int j = 1 << jj;
            if (j == 64) {                       // only in k=128 stage
                bool up = ((base & k) == 0);
                casReg(e[0], e[2], up);
                casReg(e[1], e[3], up);
            } else if (j == 32) {                // k >= 64 here
#pragma unroll
                for (int m0 = 0; m0 < 4; m0 += 2) {
                    int i = base + 32 * m0 + l;
                    bool up = ((i & k) == 0);
                    casReg(e[m0], e[m0 + 1], up);
                }
            } else {                             // j <= 16: lane shuffles
#pragma unroll
                for (int m = 0; m < 4; m++) {
                    int i = base + 32 * m + l;
                    bool up = ((i & k) == 0);
                    e[m] = casShfl(e[m], j, up, l);
                }
            }
        }
    }
}

// Bitonic merge tail (j = 64..1) for stage k >= 256: direction uniform per warp.
__device__ __forceinline__ void warpMergeTail(u64 e[4], int base, int l, int k) {
    bool up = ((base & k) == 0);
    casReg(e[0], e[2], up); casReg(e[1], e[3], up);   // j=64
    casReg(e[0], e[1], up); casReg(e[2], e[3], up);   // j=32
#pragma unroll
    for (int j = 16; j >= 1; j >>= 1)
#pragma unroll
        for (int m = 0; m < 4; m++)
            e[m] = casShfl(e[m], j, up, l);
}

__device__ __forceinline__ float blockReduceSum(float v, float* scratch) {
#pragma unroll
    for (int o = 16; o; o >>= 1) v += __shfl_down_sync(0xffffffffu, v, o);
    int w = threadIdx.x >> 5, l = threadIdx.x & 31;
    __syncthreads();
    if (l == 0) scratch[w] = v;
    __syncthreads();
    if (w == 0) {
        float t = scratch[l];   // exactly 32 warps
#pragma unroll
        for (int o = 16; o; o >>= 1) t += __shfl_down_sync(0xffffffffu, t, o);
        if (l == 0) scratch[0] = t;
    }
    __syncthreads();
    return scratch[0];
}

// SMEM: keys u64[N]; bStart i[N]; bCnt i[N]; bSum f[N]; fStart i[N+1]; fS f[N];
//       cnt i[64]; nb i[1]; red f[32]
#define SMEM_BYTES (N * 8 + (5 * N + 1) * 4 + 64 * 4 + 4 + 32 * 4 + 16)

__global__ __launch_bounds__(NTHREADS, 1)
void fusedKernel(const float* __restrict__ yhat,
                 const float* __restrict__ ytar,
                 float* __restrict__ out) {
    extern __shared__ u64 smemBase[];
    u64*   keys   = smemBase;                    // N
    int*   bStart = (int*)(keys + N);            // N
    int*   bCnt   = bStart + N;                  // N
    float* bSum   = (float*)(bCnt + N);          // N
    int*   fStart = (int*)(bSum + N);            // N+1
    float* fS     = (float*)(fStart + N + 1);    // N
    int*   cntArr = (int*)(fS + N);              // NCHUNK
    int*   nbPtr  = cntArr + NCHUNK;             // 1
    float* red    = (float*)(nbPtr + 1);         // 32

    const int tid  = threadIdx.x;
    const int row  = blockIdx.x;
    const int l    = tid & 31;
    const int wrp  = tid >> 5;
    const int base = wrp * 128;
    const float* src = row ? ytar : yhat;

    // ---- load directly into warp-strided registers, sort 128/warp ----
    u64 e[4];
#pragma unroll
    for (int m = 0; m < 4; m++) {
        int i = base + 32 * m + l;
        e[m] = ((u64)(~encodeVal(src[i])) << 32) | (u32)i;
    }
    warpSort128(e, base, l);
#pragma unroll
    for (int m = 0; m < 4; m++) keys[base + 32 * m + l] = e[m];
    __syncthreads();

    // ---- stages k=256..4096: SMEM passes for j>=128, register tail ----
    for (int k = 256; k <= N; k <<= 1) {
        for (int j = k >> 1; j >= 128; j >>= 1) {
#pragma unroll
            for (int t = 0; t < 4; ++t) {
                int i = tid + t * NTHREADS;
                int p = i ^ j;
                if (p > i) {
                    u64 a = keys[i], b = keys[p];
                    bool up = ((i & k) == 0);
                    if ((a > b) == up) { keys[i] = b; keys[p] = a; }
                }
            }
            __syncthreads();
        }
#pragma unroll
        for (int m = 0; m < 4; m++) e[m] = keys[base + 32 * m + l];
        warpMergeTail(e, base, l, k);
#pragma unroll
        for (int m = 0; m < 4; m++) keys[base + 32 * m + l] = e[m];
        __syncthreads();
    }
    // keys ascending <=> values descending, stable (asc index on ties)

    // ---- Phase A: per-chunk PAV (nonincreasing fit of z_i = s_i - (N-i)) ----
    if (tid < NCHUNK) {
        const int cbase = tid * CHUNK;
        int myCnt = 0;
        float tS  = decodeVal((u32)(keys[cbase] >> 32));
        int   tC  = 1, tSt = cbase;
        float tNum = tS - (float)(N - cbase);
        for (int i = cbase + 1; i < cbase + CHUNK; ++i) {
            float s  = decodeVal((u32)(keys[i] >> 32));
            float cS = s;
            int   cC = 1, cSt = i;
            float cNum = s - (float)(N - i);
            while (tNum * (float)cC < cNum * (float)tC) {
                cS += tS; cC += tC; cSt = tSt;
                cNum = cS - Wf(cSt, cC);
                if (myCnt == 0) { tC = 0; break; }
                myCnt--;
                tSt = bStart[cbase + myCnt];
                tS  = bSum[cbase + myCnt];
                tC  = bCnt[cbase + myCnt];
                tNum = tS - Wf(tSt, tC);
            }
            if (tC > 0) {
                bStart[cbase + myCnt] = tSt; bSum[cbase + myCnt] = tS; bCnt[cbase + myCnt] = tC;
                myCnt++;
            }
            tS = cS; tC = cC; tSt = cSt; tNum = cNum;
        }
        bStart[cbase + myCnt] = tSt; bSum[cbase + myCnt] = tS; bCnt[cbase + myCnt] = tC;
        cntArr[tid] = myCnt + 1;
    }
    __syncthreads();

    // ---- Phase B: serial merge of chunk block lists (blocks as atoms) ----
    if (tid == 0) {
        int nb = 0;
        int   tSt = bStart[0], tC = bCnt[0];
        float tS  = bSum[0];
        float tNum = tS - Wf(tSt, tC);
        for (int c = 0; c < NCHUNK; ++c) {
            int m = cntArr[c];
            for (int b = (c == 0) ? 1 : 0; b < m; ++b) {
                int off = c * CHUNK + b;
                int   cSt = bStart[off], cC = bCnt[off];
                float cS  = bSum[off];
                float cNum = cS - Wf(cSt, cC);
                while (tNum * (float)cC < cNum * (float)tC) {
                    cS += tS; cC += tC; cSt = tSt;
                    cNum = cS - Wf(cSt, cC);
                    if (nb == 0) { tC = 0; break; }
                    nb--;
                    int pSt = fStart[nb];
                    tS  = fS[nb];
                    tC  = cSt - pSt;
                    tSt = pSt;
                    tNum = tS - Wf(tSt, tC);
                }
                if (tC > 0) { fStart[nb] = tSt; fS[nb] = tS; nb++; }
                tS = cS; tC = cC; tSt = cSt; tNum = cNum;
            }
        }
        fStart[nb] = tSt; fS[nb] = tS; nb++;
        fStart[nb] = N;
        *nbPtr = nb;
    }
    __syncthreads();

    const int nb = *nbPtr;

    // ---- per-block dual mean ----
    for (int b = tid; b < nb; b += NTHREADS) {
        int s0 = fStart[b], cc = fStart[b + 1] - s0;
        fS[b] = (fS[b] - Wf(s0, cc)) / (float)cc;
    }
    __syncthreads();

    // ---- expand + scatter; accumulate own-row sums on the fly ----
    float sR = 0.f, sR2 = 0.f;
    for (int i = tid; i < N; i += NTHREADS) {
        u64 kk = keys[i];
        float s = decodeVal((u32)(kk >> 32));
        int  id = (int)(kk & 0xFFFFFFFFu);
        int lo = 0, hi = nb - 1;
        while (lo < hi) {
            int mid = (lo + hi + 1) >> 1;
            if (fStart[mid] <= i) lo = mid; else hi = mid - 1;
        }
        float r = s - fS[lo] - 2048.5f;     // shift is Spearman-invariant
        g_rank[row][id] = r;
        sR  += r;
        sR2 += r * r;
    }
    float S  = blockReduceSum(sR, red);
    float S2 = blockReduceSum(sR2, red);

    float B = 0.f;
    if (row == 1) {
        float sb = 0.f;
        for (int i = tid; i < N; i += NTHREADS) {
            float x  = yhat[i];
            float yy = ytar[i];
            sb += fmaxf(x, 0.f) + log1pf(expf(-fabsf(x))) - x * yy;
        }
        B = blockReduceSum(sb, red);
    }
    if (tid == 0) {
        g_sum[row]   = S;
        g_sumsq[row] = S2;
        if (row == 1) g_bce = B;
    }

    // ---- last-CTA-done: second finisher does the cross-term + output ----
    __threadfence();
    __syncthreads();
    __shared__ u32 who;
    if (tid == 0) who = atomicAdd(&g_arrive, 1);
    __syncthreads();
    if (who == 1) {
        __threadfence();
        float cr = 0.f;
        for (int i = tid; i < N; i += NTHREADS)
            cr += g_rank[0][i] * g_rank[1][i];
        cr = blockReduceSum(cr, red);
        if (tid == 0) {
            float invN = 1.0f / (float)N;
            float mp = g_sum[0] * invN, mt = g_sum[1] * invN;
            float varP = g_sumsq[0] - (float)N * mp * mp;
            float varT = g_sumsq[1] - (float)N * mt * mt;
            float cov  = cr - (float)N * mp * mt;
            float sp   = cov * rsqrtf(varP * varT);
            out[0] = (1.0f - sp) + g_bce * invN;
            g_arrive = 0;                    // reset for next graph replay
        }
    }
}

extern "C" void kernel_launch(void* const* d_in, const int* in_sizes, int n_in,
                              void* d_out, int out_size) {
    const float* yhat = (const float*)d_in[0];
    const float* ytar = (const float*)d_in[1];
    float* out = (float*)d_out;
    cudaFuncSetAttribute(fusedKernel,
                         cudaFuncAttributeMaxDynamicSharedMemorySize, SMEM_BYTES);
    fusedKernel<<<2, NTHREADS, SMEM_BYTES>>>(yhat, ytar, out);
}

// round 4
// speedup vs baseline: 13.3292x; 1.1965x over previous
#include <cuda_runtime.h>
#include <math.h>

#define N 4096
#define NTHREADS 1024
#define NCTA_ROW 64
#define ISLICE (N / NCTA_ROW)   // 64 elements per CTA
#define NCHUNK 64
#define CHUNK 64

typedef unsigned long long u64;
typedef unsigned int u32;

__device__ u64   g_keys[2][N];
__device__ float g_rank[2][N];
__device__ float g_sum[2], g_sumsq[2], g_bce;
__device__ u32   g_cnt[2];
__device__ u32   g_cnt2;

// ---- float -> order-preserving uint (ascending) ----
__device__ __forceinline__ u32 encodeVal(float v) {
    u32 b = __float_as_uint(v);
    return (b & 0x80000000u) ? ~b : (b | 0x80000000u);
}
// stored key hi = ~encodeVal(v)  (ascending key <=> descending value)
__device__ __forceinline__ float decodeVal(u32 khi) {
    u32 u = ~khi;
    return (u & 0x80000000u) ? __uint_as_float(u ^ 0x80000000u)
                             : __uint_as_float(~u);
}

// exact integer W(start,cnt) = cnt*N - sum(start..start+cnt-1)
__device__ __forceinline__ float Wf(int s, int c) {
    return (float)(c * N - (((2 * s + c - 1) * c) >> 1));
}

__device__ __forceinline__ float blockReduceSum(float v, float* scratch) {
#pragma unroll
    for (int o = 16; o; o >>= 1) v += __shfl_down_sync(0xffffffffu, v, o);
    int w = threadIdx.x >> 5, l = threadIdx.x & 31;
    __syncthreads();
    if (l == 0) scratch[w] = v;
    __syncthreads();
    if (w == 0) {
        float t = scratch[l];   // exactly 32 warps
#pragma unroll
        for (int o = 16; o; o >>= 1) t += __shfl_down_sync(0xffffffffu, t, o);
        if (l == 0) scratch[0] = t;
    }
    __syncthreads();
    return scratch[0];
}

// SMEM: keys u64[N]; bStart i[N]; bCnt i[N]; bSum f[N]; fStart i[N+1]; fS f[N];
//       cntArr i[64]; nb; red f[32]; who
#define SMEM_BYTES (N * 8 + (5 * N + 1) * 4 + 64 * 4 + 4 + 32 * 4 + 8 + 16)

__global__ __launch_bounds__(NTHREADS, 1)
void fusedKernel(const float* __restrict__ yhat,
                 const float* __restrict__ ytar,
                 float* __restrict__ out) {
    extern __shared__ u64 smemBase[];
    u64*   keys   = smemBase;                    // N
    int*   bStart = (int*)(keys + N);            // N
    int*   bCnt   = bStart + N;                  // N
    float* bSum   = (float*)(bCnt + N);          // N
    int*   fStart = (int*)(bSum + N);            // N+1
    float* fS     = (float*)(fStart + N + 1);    // N
    int*   cntArr = (int*)(fS + N);              // NCHUNK
    int*   nbPtr  = cntArr + NCHUNK;             // 1
    float* red    = (float*)(nbPtr + 1);         // 32
    u32*   shWho  = (u32*)(red + 32);            // 2

    u32* eArr = (u32*)bStart;   // counting-phase reuse (16KB)

    const int tid  = threadIdx.x;
    const int row  = blockIdx.x >> 6;
    const int slot = blockIdx.x & (NCTA_ROW - 1);
    const float* src = row ? ytar : yhat;

    // ================= Phase 1: rank-by-counting (all 128 CTAs) =============
    {
        float4 v = ((const float4*)src)[tid];
        uint4 ev;
        ev.x = ~encodeVal(v.x); ev.y = ~encodeVal(v.y);
        ev.z = ~encodeVal(v.z); ev.w = ~encodeVal(v.w);
        ((uint4*)eArr)[tid] = ev;
    }
    __syncthreads();

    {
        const int lane = tid & 31;
        const int part = tid & 15;                  // j-partition 0..15
        const int i    = slot * ISLICE + (tid >> 4);
        const u32 ei   = eArr[i];
        const int d    = i - part;
        const int jlim = (d > 0) ? ((d + 15) >> 4) : 0;  // jj<jlim <=> j<i
        u32 c = 0;
#pragma unroll 16
        for (int jj = 0; jj < 256; ++jj) {
            u32 a = eArr[jj * 16 + part];           // 16 banks + broadcast: conflict-free
            c += (u32)(a < ei) + ((u32)(a == ei) & (u32)(jj < jlim));
        }
        u32 pos = __reduce_add_sync(0xFFFFu << (lane & 16), c);
        if (part == 0)
            g_keys[row][pos] = ((u64)ei << 32) | (u32)i;
    }

    // arrival gate: last CTA of this row continues with PAV
    __threadfence();
    __syncthreads();
    if (tid == 0) shWho[0] = atomicAdd(&g_cnt[row], 1);
    __syncthreads();
    if (shWho[0] != NCTA_ROW - 1) return;
    __threadfence();   // acquire: other CTAs' g_keys writes

    // ================= Phase 2: PAV on sorted keys (1 CTA per row) ==========
    {
        const u64* gk = g_keys[row];
#pragma unroll
        for (int m = 0; m < 4; m++) {
            int i = tid + m * NTHREADS;
            keys[i] = gk[i];
        }
    }
    __syncthreads();

    // ---- Phase A: per-chunk PAV (nonincreasing fit of z_i = s_i - (N-i)) ----
    if (tid < NCHUNK) {
        const int cbase = tid * CHUNK;
        int myCnt = 0;
        float tS  = decodeVal((u32)(keys[cbase] >> 32));
        int   tC  = 1, tSt = cbase;
        float tNum = tS - (float)(N - cbase);
        for (int i = cbase + 1; i < cbase + CHUNK; ++i) {
            float s  = decodeVal((u32)(keys[i] >> 32));
            float cS = s;
            int   cC = 1, cSt = i;
            float cNum = s - (float)(N - i);
            while (tNum * (float)cC < cNum * (float)tC) {
                cS += tS; cC += tC; cSt = tSt;
                cNum = cS - Wf(cSt, cC);
                if (myCnt == 0) { tC = 0; break; }
                myCnt--;
                tSt = bStart[cbase + myCnt];
                tS  = bSum[cbase + myCnt];
                tC  = bCnt[cbase + myCnt];
                tNum = tS - Wf(tSt, tC);
            }
            if (tC > 0) {
                bStart[cbase + myCnt] = tSt; bSum[cbase + myCnt] = tS; bCnt[cbase + myCnt] = tC;
                myCnt++;
            }
            tS = cS; tC = cC; tSt = cSt; tNum = cNum;
        }
        bStart[cbase + myCnt] = tSt; bSum[cbase + myCnt] = tS; bCnt[cbase + myCnt] = tC;
        cntArr[tid] = myCnt + 1;
    }
    __syncthreads();

    // ---- Phase B: serial merge of chunk block lists (blocks as atoms) ----
    if (tid == 0) {
        int nb = 0;
        int   tSt = bStart[0], tC = bCnt[0];
        float tS  = bSum[0];
        float tNum = tS - Wf(tSt, tC);
        for (int c = 0; c < NCHUNK; ++c) {
            int m = cntArr[c];
            for (int b = (c == 0) ? 1 : 0; b < m; ++b) {
                int off = c * CHUNK + b;
                int   cSt = bStart[off], cC = bCnt[off];
                float cS  = bSum[off];
                float cNum = cS - Wf(cSt, cC);
                while (tNum * (float)cC < cNum * (float)tC) {
                    cS += tS; cC += tC; cSt = tSt;
                    cNum = cS - Wf(cSt, cC);
                    if (nb == 0) { tC = 0; break; }
                    nb--;
                    int pSt = fStart[nb];
                    tS  = fS[nb];
                    tC  = cSt - pSt;
                    tSt = pSt;
                    tNum = tS - Wf(tSt, tC);
                }
                if (tC > 0) { fStart[nb] = tSt; fS[nb] = tS; nb++; }
                tS = cS; tC = cC; tSt = cSt; tNum = cNum;
            }
        }
        fStart[nb] = tSt; fS[nb] = tS; nb++;
        fStart[nb] = N;
        *nbPtr = nb;
    }
    __syncthreads();

    const int nb = *nbPtr;

    // ---- per-block dual mean ----
    for (int b = tid; b < nb; b += NTHREADS) {
        int s0 = fStart[b], cc = fStart[b + 1] - s0;
        fS[b] = (fS[b] - Wf(s0, cc)) / (float)cc;
    }
    __syncthreads();

    // ---- expand + scatter; keep local copy; accumulate own-row sums ----
    float* rLocal = bSum;    // bSum free after Phase B
    float sR = 0.f, sR2 = 0.f;
    for (int i = tid; i < N; i += NTHREADS) {
        u64 kk = keys[i];
        float s = decodeVal((u32)(kk >> 32));
        int  id = (int)(kk & 0xFFFFFFFFu);
        int lo = 0, hi = nb - 1;
        while (lo < hi) {
            int mid = (lo + hi + 1) >> 1;
            if (fStart[mid] <= i) lo = mid; else hi = mid - 1;
        }
        float r = s - fS[lo] - 2048.5f;    // shift is Spearman-invariant
        g_rank[row][id] = r;
        rLocal[id] = r;
        sR  += r;
        sR2 += r * r;
    }
    float S  = blockReduceSum(sR, red);
    float S2 = blockReduceSum(sR2, red);

    float B = 0.f;
    if (row == 1) {
        float sb = 0.f;
        for (int i = tid; i < N; i += NTHREADS) {
            float x  = yhat[i];
            float yy = ytar[i];
            sb += fmaxf(x, 0.f) + log1pf(expf(-fabsf(x))) - x * yy;
        }
        B = blockReduceSum(sb, red);
    }
    if (tid == 0) {
        g_sum[row]   = S;
        g_sumsq[row] = S2;
        if (row == 1) g_bce = B;
    }

    // ================= Phase 3: last PAV CTA finishes ========================
    __threadfence();
    __syncthreads();
    if (tid == 0) shWho[1] = atomicAdd(&g_cnt2, 1);
    __syncthreads();
    if (shWho[1] != 1) return;
    __threadfence();

    {
        const float* other = g_rank[1 - row];
        float cr = 0.f;
        for (int i = tid; i < N; i += NTHREADS)
            cr += other[i] * rLocal[i];
        cr = blockReduceSum(cr, red);
        if (tid == 0) {
            float invN = 1.0f / (float)N;
            float mp = g_sum[0] * invN, mt = g_sum[1] * invN;
            float varP = g_sumsq[0] - (float)N * mp * mp;
            float varT = g_sumsq[1] - (float)N * mt * mt;
            float cov  = cr - (float)N * mp * mt;
            float sp   = cov * rsqrtf(varP * varT);
            out[0] = (1.0f - sp) + g_bce * invN;
            g_cnt[0] = 0; g_cnt[1] = 0; g_cnt2 = 0;   // reset for graph replay
        }
    }
}

extern "C" void kernel_launch(void* const* d_in, const int* in_sizes, int n_in,
                              void* d_out, int out_size) {
    const float* yhat = (const float*)d_in[0];
    const float* ytar = (const float*)d_in[1];
    float* out = (float*)d_out;
    cudaFuncSetAttribute(fusedKernel,
                         cudaFuncAttributeMaxDynamicSharedMemorySize, SMEM_BYTES);
    fusedKernel<<<2 * NCTA_ROW, NTHREADS, SMEM_BYTES>>>(yhat, ytar, out);
}

// round 5
// speedup vs baseline: 16.6840x; 1.2517x over previous
#include <cuda_runtime.h>
#include <math.h>

#define N 4096
#define NTHREADS 1024
#define NCTA_ROW 64
#define ISLICE (N / NCTA_ROW)   // 64 targets per CTA
#define NCHUNK 64
#define CHUNK 64

typedef unsigned long long u64;
typedef unsigned int u32;

__device__ u64   g_keys[2][N];
__device__ float g_rank[2][N];
__device__ float g_sum[2], g_sumsq[2], g_bce;
__device__ u32   g_cnt[2];
__device__ u32   g_cnt2;

// ---- float -> order-preserving uint (ascending) ----
__device__ __forceinline__ u32 encodeVal(float v) {
    u32 b = __float_as_uint(v);
    return (b & 0x80000000u) ? ~b : (b | 0x80000000u);
}
// stored key hi = ~encodeVal(v)  (ascending key <=> descending value)
__device__ __forceinline__ float decodeVal(u32 khi) {
    u32 u = ~khi;
    return (u & 0x80000000u) ? __uint_as_float(u ^ 0x80000000u)
                             : __uint_as_float(~u);
}

// exact integer W(start,cnt) = cnt*N - sum(start..start+cnt-1)
__device__ __forceinline__ float Wf(int s, int c) {
    return (float)(c * N - (((2 * s + c - 1) * c) >> 1));
}

__device__ __forceinline__ float blockReduceSum(float v, float* scratch) {
#pragma unroll
    for (int o = 16; o; o >>= 1) v += __shfl_down_sync(0xffffffffu, v, o);
    int w = threadIdx.x >> 5, l = threadIdx.x & 31;
    __syncthreads();
    if (l == 0) scratch[w] = v;
    __syncthreads();
    if (w == 0) {
        float t = scratch[l];   // exactly 32 warps
#pragma unroll
        for (int o = 16; o; o >>= 1) t += __shfl_down_sync(0xffffffffu, t, o);
        if (l == 0) scratch[0] = t;
    }
    __syncthreads();
    return scratch[0];
}

// SMEM: keys u64[N]; bStart i[N]; bCnt i[N]; bSum f[N]; fStart i[N+1]; fS f[N];
//       cntArr i[64]; nb; red f[32]; who
#define SMEM_BYTES (N * 8 + (5 * N + 1) * 4 + 64 * 4 + 4 + 32 * 4 + 8 + 16)

__global__ __launch_bounds__(NTHREADS, 1)
void fusedKernel(const float* __restrict__ yhat,
                 const float* __restrict__ ytar,
                 float* __restrict__ out) {
    extern __shared__ u64 smemBase[];
    u64*   keys   = smemBase;                    // N
    int*   bStart = (int*)(keys + N);            // N
    int*   bCnt   = bStart + N;                  // N
    float* bSum   = (float*)(bCnt + N);          // N
    int*   fStart = (int*)(bSum + N);            // N+1
    float* fS     = (float*)(fStart + N + 1);    // N
    int*   cntArr = (int*)(fS + N);              // NCHUNK
    int*   nbPtr  = cntArr + NCHUNK;             // 1
    float* red    = (float*)(nbPtr + 1);         // 32
    u32*   shWho  = (u32*)(red + 32);            // 2

    u32* eArr = (u32*)bStart;   // counting-phase reuse (16KB)

    const int tid  = threadIdx.x;
    const int row  = blockIdx.x >> 6;
    const int slot = blockIdx.x & (NCTA_ROW - 1);
    const float* src = row ? ytar : yhat;

    // ================= Phase 1: rank-by-counting (all 128 CTAs) =============
    {
        float4 v = ((const float4*)src)[tid];
        uint4 ev;
        ev.x = ~encodeVal(v.x); ev.y = ~encodeVal(v.y);
        ev.z = ~encodeVal(v.z); ev.w = ~encodeVal(v.w);
        ((uint4*)eArr)[tid] = ev;
    }
    __syncthreads();

    {
        const int lane = tid & 31;
        const int p    = tid & 15;                 // 16 threads per target
        const int i    = slot * ISLICE + (tid >> 4);
        const u32 ei   = eArr[i];
        const uint4* qp = (const uint4*)eArr;      // 1024 quads of 4 keys
        const int Qs   = i >> 2;                   // straddling quad
        // thread p owns quads Q = 16t + p; quads Q < Qs are fully below i
        int tsplit = (Qs - p + 15) >> 4;           // in [0, 64]
        u32 c = 0;
        int t = 0;
#pragma unroll 4
        for (; t < tsplit; ++t) {                  // j < i : count a <= ei
            uint4 a = qp[(t << 4) + p];
            c += (u32)(a.x <= ei) + (u32)(a.y <= ei)
               + (u32)(a.z <= ei) + (u32)(a.w <= ei);
        }
#pragma unroll 4
        for (; t < 64; ++t) {                      // j >= i : count a < ei
            uint4 a = qp[(t << 4) + p];
            c += (u32)(a.x < ei) + (u32)(a.y < ei)
               + (u32)(a.z < ei) + (u32)(a.w < ei);
        }
        // straddling quad fixup: elements j in [4Qs, i) were counted with '<',
        // need '<=' -> add back equality matches
        if ((Qs & 15) == p) {
            int rem = i & 3;
            for (int r = 0; r < rem; ++r)
                c += (u32)(eArr[(Qs << 2) + r] == ei);
        }
        u32 pos = __reduce_add_sync(0xFFFFu << (lane & 16), c);
        if (p == 0)
            g_keys[row][pos] = ((u64)ei << 32) | (u32)i;
    }

    // arrival gate: last CTA of this row continues with PAV
    __threadfence();
    __syncthreads();
    if (tid == 0) shWho[0] = atomicAdd(&g_cnt[row], 1);
    __syncthreads();
    if (shWho[0] != NCTA_ROW - 1) return;
    __threadfence();   // acquire: other CTAs' g_keys writes

    // ================= Phase 2: PAV on sorted keys (1 CTA per row) ==========
    {
        const u64* gk = g_keys[row];
#pragma unroll
        for (int m = 0; m < 4; m++) {
            int i = tid + m * NTHREADS;
            keys[i] = gk[i];
        }
    }
    __syncthreads();

    // ---- Phase A: per-chunk PAV (nonincreasing fit of z_i = s_i - (N-i)) ----
    if (tid < NCHUNK) {
        const int cbase = tid * CHUNK;
        int myCnt = 0;
        float tS  = decodeVal((u32)(keys[cbase] >> 32));
        int   tC  = 1, tSt = cbase;
        float tNum = tS - (float)(N - cbase);
        for (int i = cbase + 1; i < cbase + CHUNK; ++i) {
            float s  = decodeVal((u32)(keys[i] >> 32));
            float cS = s;
            int   cC = 1, cSt = i;
            float cNum = s - (float)(N - i);
            while (tNum * (float)cC < cNum * (float)tC) {
                cS += tS; cC += tC; cSt = tSt;
                cNum = cS - Wf(cSt, cC);
                if (myCnt == 0) { tC = 0; break; }
                myCnt--;
                tSt = bStart[cbase + myCnt];
                tS  = bSum[cbase + myCnt];
                tC  = bCnt[cbase + myCnt];
                tNum = tS - Wf(tSt, tC);
            }
            if (tC > 0) {
                bStart[cbase + myCnt] = tSt; bSum[cbase + myCnt] = tS; bCnt[cbase + myCnt] = tC;
                myCnt++;
            }
            tS = cS; tC = cC; tSt = cSt; tNum = cNum;
        }
        bStart[cbase + myCnt] = tSt; bSum[cbase + myCnt] = tS; bCnt[cbase + myCnt] = tC;
        cntArr[tid] = myCnt + 1;
    }
    __syncthreads();

    // ---- Phase B: serial merge of chunk block lists (blocks as atoms) ----
    if (tid == 0) {
        int nb = 0;
        int   tSt = bStart[0], tC = bCnt[0];
        float tS  = bSum[0];
        float tNum = tS - Wf(tSt, tC);
        for (int c = 0; c < NCHUNK; ++c) {
            int m = cntArr[c];
            for (int b = (c == 0) ? 1 : 0; b < m; ++b) {
                int off = c * CHUNK + b;
                int   cSt = bStart[off], cC = bCnt[off];
                float cS  = bSum[off];
                float cNum = cS - Wf(cSt, cC);
                while (tNum * (float)cC < cNum * (float)tC) {
                    cS += tS; cC += tC; cSt = tSt;
                    cNum = cS - Wf(cSt, cC);
                    if (nb == 0) { tC = 0; break; }
                    nb--;
                    int pSt = fStart[nb];
                    tS  = fS[nb];
                    tC  = cSt - pSt;
                    tSt = pSt;
                    tNum = tS - Wf(tSt, tC);
                }
                if (tC > 0) { fStart[nb] = tSt; fS[nb] = tS; nb++; }
                tS = cS; tC = cC; tSt = cSt; tNum = cNum;
            }
        }
        fStart[nb] = tSt; fS[nb] = tS; nb++;
        fStart[nb] = N;
        *nbPtr = nb;
    }
    __syncthreads();

    const int nb = *nbPtr;

    // ---- per-block dual mean ----
    for (int b = tid; b < nb; b += NTHREADS) {
        int s0 = fStart[b], cc = fStart[b + 1] - s0;
        fS[b] = (fS[b] - Wf(s0, cc)) / (float)cc;
    }
    __syncthreads();

    // ---- expand + scatter; keep local copy; accumulate own-row sums ----
    float* rLocal = bSum;    // bSum free after Phase B
    float sR = 0.f, sR2 = 0.f;
    for (int i = tid; i < N; i += NTHREADS) {
        u64 kk = keys[i];
        float s = decodeVal((u32)(kk >> 32));
        int  id = (int)(kk & 0xFFFFFFFFu);
        int lo = 0, hi = nb - 1;
        while (lo < hi) {
            int mid = (lo + hi + 1) >> 1;
            if (fStart[mid] <= i) lo = mid; else hi = mid - 1;
        }
        float r = s - fS[lo] - 2048.5f;    // shift is Spearman-invariant
        g_rank[row][id] = r;
        rLocal[id] = r;
        sR  += r;
        sR2 += r * r;
    }
    float S  = blockReduceSum(sR, red);
    float S2 = blockReduceSum(sR2, red);

    float B = 0.f;
    if (row == 1) {
        float sb = 0.f;
        for (int i = tid; i < N; i += NTHREADS) {
            float x  = yhat[i];
            float yy = ytar[i];
            sb += fmaxf(x, 0.f) + log1pf(expf(-fabsf(x))) - x * yy;
        }
        B = blockReduceSum(sb, red);
    }
    if (tid == 0) {
        g_sum[row]   = S;
        g_sumsq[row] = S2;
        if (row == 1) g_bce = B;
    }

    // ================= Phase 3: last PAV CTA finishes ========================
    __threadfence();
    __syncthreads();
    if (tid == 0) shWho[1] = atomicAdd(&g_cnt2, 1);
    __syncthreads();
    if (shWho[1] != 1) return;
    __threadfence();

    {
        const float* other = g_rank[1 - row];
        float cr = 0.f;
        for (int i = tid; i < N; i += NTHREADS)
            cr += other[i] * rLocal[i];
        cr = blockReduceSum(cr, red);
        if (tid == 0) {
            float invN = 1.0f / (float)N;
            float mp = g_sum[0] * invN, mt = g_sum[1] * invN;
            float varP = g_sumsq[0] - (float)N * mp * mp;
            float varT = g_sumsq[1] - (float)N * mt * mt;
            float cov  = cr - (float)N * mp * mt;
            float sp   = cov * rsqrtf(varP * varT);
            out[0] = (1.0f - sp) + g_bce * invN;
            g_cnt[0] = 0; g_cnt[1] = 0; g_cnt2 = 0;   // reset for graph replay
        }
    }
}

extern "C" void kernel_launch(void* const* d_in, const int* in_sizes, int n_in,
                              void* d_out, int out_size) {
    const float* yhat = (const float*)d_in[0];
    const float* ytar = (const float*)d_in[1];
    float* out = (float*)d_out;
    cudaFuncSetAttribute(fusedKernel,
                         cudaFuncAttributeMaxDynamicSharedMemorySize, SMEM_BYTES);
    fusedKernel<<<2 * NCTA_ROW, NTHREADS, SMEM_BYTES>>>(yhat, ytar, out);
}